// round 4
// baseline (speedup 1.0000x reference)
#include <cuda_runtime.h>
#include <cuda_bf16.h>

// SegmentalEmotion: per-sample sliding-window segment means (2-kernel).
// H: [B, T, D] fp32, lengths_sec: [B] fp32.
// Output: S_pad [B, maxS, D] fp32 (+ mask [B, maxS] fp32 appended, auto-detect).
//
// Plan (matches numpy fp64 bit-for-bit) computed per block by thread 0 only:
//   dur = max(len, 0.001); fps = T/dur
//   win = max(1, rint(fps)); hop = max(1, rint(fps*0.5))
//   n = (T >= win) ? (T-win)/hop + 1 : 0 ; n==0 -> fallback full-T mean
//
// Phase 1: hop-chunks split into <=4 uniform pieces (~19-38 frames each);
//          reads H exactly once with streaming loads, writes piece sums to g_P.
// Phase 2: window s = pieces of chunk s + chunk s+1 (+/- <=1 edge frame),
//          scale by 1/win, write output + mask.

#define T_FRAMES 1500
#define D_DIM    768
#define D_VEC    (D_DIM / 4)   // 192 float4 lanes
#define NTHREADS 192
#define MAX_B    32
#define MAX_NHOP 60            // ceil(1500/25)
#define MAX_NP   4
#define MAX_PIECES 80          // max nhop*np over hop range (78 @ hop~39)
#define PIECE_TGT 38           // target frames per phase-1 block

// piece sums: P[b, j, p, :]
__device__ float g_P[(size_t)MAX_B * MAX_NHOP * MAX_NP * D_DIM];

struct Plan { int win, hop, n_eff, nhop, np, plen, fallback; };

// fp64 plan — call from ONE thread per block only.
__device__ __forceinline__ Plan compute_plan(float len)
{
    Plan p;
    double dur = fmax((double)len, 0.001);
    double fps = (double)T_FRAMES / dur;
    long long win = llrint(fps);        if (win < 1) win = 1;   // WIN_SEC = 1.0
    long long hop = llrint(fps * 0.5);  if (hop < 1) hop = 1;   // HOP_SEC = 0.5
    long long n = ((long long)T_FRAMES >= win)
                      ? ((long long)T_FRAMES - win) / hop + 1 : 0;
    p.fallback = (n == 0);
    if (win > T_FRAMES + 1) win = T_FRAMES + 1;   // unused when fallback
    if (hop > T_FRAMES) hop = T_FRAMES;
    p.win   = (int)win;
    p.hop   = (int)hop;
    p.n_eff = (int)(p.fallback ? 1 : n);
    p.nhop  = (int)((T_FRAMES + hop - 1) / hop);
    int np = (p.hop + PIECE_TGT - 1) / PIECE_TGT;
    if (np > MAX_NP) np = MAX_NP;
    p.np   = np;
    p.plen = (p.hop + np - 1) / np;
    return p;
}

// ---------- Phase 1: uniform piece sums, reads H exactly once ----------
__global__ __launch_bounds__(NTHREADS)
void piece_sum_kernel(const float* __restrict__ H,
                      const float* __restrict__ lens)
{
    const int m   = blockIdx.x;   // linear (chunk, piece) index
    const int b   = blockIdx.y;
    const int tid = threadIdx.x;

    __shared__ Plan sp;
    if (tid == 0) sp = compute_plan(lens[b]);
    __syncthreads();

    const int np = sp.np;
    if (m >= sp.nhop * np) return;
    const int j = m / np;
    const int p = m - j * np;

    const int hop  = sp.hop;
    const int plen = sp.plen;

    int t0 = j * hop + p * plen;
    int chunk_end = j * hop + hop;
    if (chunk_end > T_FRAMES) chunk_end = T_FRAMES;
    int t1 = t0 + plen;
    if (t1 > chunk_end) t1 = chunk_end;

    const float4* __restrict__ Hb =
        (const float4*)H + (size_t)b * T_FRAMES * D_VEC + tid;

    float4 acc = make_float4(0.f, 0.f, 0.f, 0.f);
    int t = t0;
    for (; t + 8 <= t1; t += 8) {
        float4 v0 = __ldcs(&Hb[(t + 0) * D_VEC]);
        float4 v1 = __ldcs(&Hb[(t + 1) * D_VEC]);
        float4 v2 = __ldcs(&Hb[(t + 2) * D_VEC]);
        float4 v3 = __ldcs(&Hb[(t + 3) * D_VEC]);
        float4 v4 = __ldcs(&Hb[(t + 4) * D_VEC]);
        float4 v5 = __ldcs(&Hb[(t + 5) * D_VEC]);
        float4 v6 = __ldcs(&Hb[(t + 6) * D_VEC]);
        float4 v7 = __ldcs(&Hb[(t + 7) * D_VEC]);
        acc.x += v0.x + v1.x + v2.x + v3.x + v4.x + v5.x + v6.x + v7.x;
        acc.y += v0.y + v1.y + v2.y + v3.y + v4.y + v5.y + v6.y + v7.y;
        acc.z += v0.z + v1.z + v2.z + v3.z + v4.z + v5.z + v6.z + v7.z;
        acc.w += v0.w + v1.w + v2.w + v3.w + v4.w + v5.w + v6.w + v7.w;
    }
    for (; t < t1; ++t) {
        float4 v = __ldcs(&Hb[t * D_VEC]);
        acc.x += v.x; acc.y += v.y; acc.z += v.z; acc.w += v.w;
    }

    ((float4*)g_P)[(((size_t)b * MAX_NHOP + j) * MAX_NP + p) * D_VEC + tid] = acc;
}

// ---------- Phase 2: combine piece sums + edge correction ----------
__global__ __launch_bounds__(NTHREADS)
void seg_out_kernel(const float* __restrict__ H,
                    const float* __restrict__ lens,
                    float* __restrict__ S,      // [B, maxS, D]
                    float* __restrict__ Mout,   // [B, maxS] or nullptr
                    int maxS)
{
    const int s   = blockIdx.x;
    const int b   = blockIdx.y;
    const int tid = threadIdx.x;

    __shared__ Plan sp;
    if (tid == 0) sp = compute_plan(lens[b]);
    __syncthreads();

    float4* outRow = (float4*)(S + ((size_t)b * maxS + s) * D_DIM);

    if (s >= sp.n_eff) {
        outRow[tid] = make_float4(0.f, 0.f, 0.f, 0.f);
        if (Mout != nullptr && tid == 0)
            Mout[(size_t)b * maxS + s] = 0.f;
        return;
    }

    const int win  = sp.win;
    const int hop  = sp.hop;
    const int nhop = sp.nhop;
    const int np   = sp.np;

    const float4* __restrict__ Pb =
        (const float4*)g_P + (size_t)b * MAX_NHOP * MAX_NP * D_VEC + tid;
    const float4* __restrict__ Hb =
        (const float4*)H + (size_t)b * T_FRAMES * D_VEC + tid;

    float4 acc = make_float4(0.f, 0.f, 0.f, 0.f);
    int cnt;

    if (sp.fallback) {
        for (int j = 0; j < nhop; ++j)
            for (int p = 0; p < np; ++p) {
                float4 v = Pb[((size_t)j * MAX_NP + p) * D_VEC];
                acc.x += v.x; acc.y += v.y; acc.z += v.z; acc.w += v.w;
            }
        cnt = T_FRAMES;
    } else {
        const int start = s * hop;
        const int end   = start + win;           // <= T by definition of n
        const bool have2 = (s + 1) < nhop;

        #pragma unroll
        for (int p = 0; p < MAX_NP; ++p) {
            if (p < np) {
                float4 v = Pb[((size_t)s * MAX_NP + p) * D_VEC];
                acc.x += v.x; acc.y += v.y; acc.z += v.z; acc.w += v.w;
            }
        }
        if (have2) {
            #pragma unroll
            for (int p = 0; p < MAX_NP; ++p) {
                if (p < np) {
                    float4 v = Pb[((size_t)(s + 1) * MAX_NP + p) * D_VEC];
                    acc.x += v.x; acc.y += v.y; acc.z += v.z; acc.w += v.w;
                }
            }
        }
        // chunks s (+ s+1) cover [start, cov_end)
        int cov_end = start + (have2 ? 2 : 1) * hop;
        if (cov_end > T_FRAMES) cov_end = T_FRAMES;

        for (int t = cov_end; t < end; ++t) {     // add missing (<=1 in practice)
            float4 v = Hb[t * D_VEC];
            acc.x += v.x; acc.y += v.y; acc.z += v.z; acc.w += v.w;
        }
        for (int t = end; t < cov_end; ++t) {     // subtract excess (<=1)
            float4 v = Hb[t * D_VEC];
            acc.x -= v.x; acc.y -= v.y; acc.z -= v.z; acc.w -= v.w;
        }
        cnt = win > 0 ? win : 1;
    }

    const float inv = 1.0f / (float)cnt;
    outRow[tid] = make_float4(acc.x * inv, acc.y * inv, acc.z * inv, acc.w * inv);
    if (Mout != nullptr && tid == 0)
        Mout[(size_t)b * maxS + s] = 1.f;
}

extern "C" void kernel_launch(void* const* d_in, const int* in_sizes, int n_in,
                              void* d_out, int out_size)
{
    const float* H    = (const float*)d_in[0];
    const float* lens = (const float*)d_in[1];
    float* out        = (float*)d_out;

    const int B = in_sizes[1];  // 32

    // Infer maxS and mask presence from out_size (768, 769 coprime; maxS << 768).
    int maxS;
    bool has_mask;
    if (out_size % (B * (D_DIM + 1)) == 0) {
        maxS = out_size / (B * (D_DIM + 1));
        has_mask = true;
    } else {
        maxS = out_size / (B * D_DIM);
        has_mask = false;
    }

    float* Mout = has_mask ? (out + (size_t)B * maxS * D_DIM) : nullptr;

    dim3 grid1(MAX_PIECES, B);
    piece_sum_kernel<<<grid1, NTHREADS>>>(H, lens);

    dim3 grid2(maxS, B);
    seg_out_kernel<<<grid2, NTHREADS>>>(H, lens, out, Mout, maxS);
}